// round 2
// baseline (speedup 1.0000x reference)
#include <cuda_runtime.h>

#define OUT_HW 7
#define NBINS 49
#define SN 2
#define SPATIAL_SCALE 0.25f
#define CC 256
#define HH 200
#define WW 272
#define BB 4
#define HWSZ (HH * WW)

// Scratch: NHWC copy of features (~223 MB). Device global => no runtime alloc.
__device__ float g_nhwc[(size_t)BB * HWSZ * CC];

// NCHW [B,C,H,W] -> NHWC [B,H,W,C]. Per-batch [C, HW] -> [HW, C] tiled transpose.
__global__ void nchw_to_nhwc(const float* __restrict__ in) {
    __shared__ float tile[32][33];
    const int b   = blockIdx.z;
    const int hw0 = blockIdx.x * 32;
    const int c0  = blockIdx.y * 32;
    const int tx = threadIdx.x, ty = threadIdx.y;
    const float* src = in + (size_t)b * CC * HWSZ;
    float* dst = g_nhwc + (size_t)b * HWSZ * CC;
#pragma unroll
    for (int k = 0; k < 4; k++) {
        int c = c0 + ty + k * 8;
        tile[ty + k * 8][tx] = src[(size_t)c * HWSZ + hw0 + tx];
    }
    __syncthreads();
#pragma unroll
    for (int k = 0; k < 4; k++) {
        int hw = hw0 + ty + k * 8;
        dst[(size_t)hw * CC + c0 + tx] = tile[tx][ty + k * 8];
    }
}

// One block per roi. blockDim = (32, 8): x = channel float4 group, y = bin slot.
// Two channel halves of 128; results staged in smem in output layout, then
// copied out linearly (fully coalesced).
__global__ __launch_bounds__(256) void roi_align_kernel(
    const float* __restrict__ rois, float* __restrict__ out) {
    const int n = blockIdx.x;

    __shared__ int   s_i0[28];    // [0..13] y0, [14..27] x0
    __shared__ float s_l[28];     // frac part
    __shared__ int   s_v[28];     // valid flag
    __shared__ int   s_b;
    __shared__ float sbuf[128 * NBINS];   // 25,088 B

    const int tx = threadIdx.x, ty = threadIdx.y;
    const int tid = ty * 32 + tx;

    if (tid < 28) {
        const bool isx = tid >= 14;
        const int j = isx ? tid - 14 : tid;
        const float lo = rois[n * 5 + (isx ? 1 : 2)] * SPATIAL_SCALE;
        const float hi = rois[n * 5 + (isx ? 3 : 4)] * SPATIAL_SCALE;
        const float sz  = fmaxf(hi - lo, 1.0f);
        const float bin = sz * (1.0f / (float)OUT_HW);
        const float p = ((float)j + 0.5f) * 0.5f;     // (j+0.5)/SN
        const float coord = lo + p * bin;
        const int lim = isx ? WW : HH;
        const int valid = (coord > -1.0f) && (coord < (float)lim);
        float cc = fminf(fmaxf(coord, 0.0f), (float)(lim - 1));
        float c0 = fminf(floorf(cc), (float)(lim - 2));
        s_i0[tid] = (int)c0;
        s_l[tid]  = cc - c0;
        s_v[tid]  = valid;
    }
    if (tid == 0) s_b = (int)rois[n * 5 + 0];
    __syncthreads();

    const float* fbase = g_nhwc + (size_t)s_b * HWSZ * CC;

    for (int cg = 0; cg < 2; cg++) {
        const int c = cg * 128 + tx * 4;

        for (int bin = ty; bin < NBINS; bin += 8) {
            const int ph = bin / 7;
            const int pw = bin - ph * 7;
            float ax = 0.f, ay = 0.f, az = 0.f, aw = 0.f;
#pragma unroll
            for (int sy = 0; sy < 2; sy++) {
#pragma unroll
                for (int sx = 0; sx < 2; sx++) {
                    const int jy = ph * 2 + sy;
                    const int jx = 14 + pw * 2 + sx;
                    if (s_v[jy] && s_v[jx]) {
                        const int   y0 = s_i0[jy];
                        const int   x0 = s_i0[jx];
                        const float ly = s_l[jy];
                        const float lx = s_l[jx];
                        const float hy = 1.0f - ly, hx = 1.0f - lx;
                        const float* p00 =
                            fbase + ((size_t)(y0 * WW + x0)) * CC + c;
                        const float4 v00 = *(const float4*)(p00);
                        const float4 v01 = *(const float4*)(p00 + CC);
                        const float4 v10 = *(const float4*)(p00 + (size_t)WW * CC);
                        const float4 v11 = *(const float4*)(p00 + (size_t)WW * CC + CC);
                        const float w00 = hy * hx, w01 = hy * lx;
                        const float w10 = ly * hx, w11 = ly * lx;
                        ax += w00 * v00.x + w01 * v01.x + w10 * v10.x + w11 * v11.x;
                        ay += w00 * v00.y + w01 * v01.y + w10 * v10.y + w11 * v11.y;
                        az += w00 * v00.z + w01 * v01.z + w10 * v10.z + w11 * v11.z;
                        aw += w00 * v00.w + w01 * v01.w + w10 * v10.w + w11 * v11.w;
                    }
                }
            }
            const int cl = tx * 4;
            sbuf[(cl + 0) * NBINS + bin] = ax * 0.25f;
            sbuf[(cl + 1) * NBINS + bin] = ay * 0.25f;
            sbuf[(cl + 2) * NBINS + bin] = az * 0.25f;
            sbuf[(cl + 3) * NBINS + bin] = aw * 0.25f;
        }
        __syncthreads();

        // Coalesced linear copy-out: this half is contiguous in the output.
        float* o = out + (size_t)n * (CC * NBINS) + (size_t)cg * 128 * NBINS;
        for (int i = tid; i < 128 * NBINS; i += 256) o[i] = sbuf[i];
        __syncthreads();
    }
}

extern "C" void kernel_launch(void* const* d_in, const int* in_sizes, int n_in,
                              void* d_out, int out_size) {
    const float* features = (const float*)d_in[0];
    const float* rois     = (const float*)d_in[1];
    float* out            = (float*)d_out;
    const int nrois = in_sizes[1] / 5;

    dim3 tgrid(HWSZ / 32, CC / 32, BB);   // 1700 x 8 x 4
    nchw_to_nhwc<<<tgrid, dim3(32, 8)>>>(features);
    roi_align_kernel<<<nrois, dim3(32, 8)>>>(rois, out);
}

// round 3
// speedup vs baseline: 1.4120x; 1.4120x over previous
#include <cuda_runtime.h>
#include <cuda_fp16.h>

#define OUT_HW 7
#define NBINS 49
#define SPATIAL_SCALE 0.25f
#define CC 256
#define HH 200
#define WW 272
#define BB 4
#define HWSZ (HH * WW)

// Scratch: NHWC fp16 copy of features (~111 MB) -> fits in GB300's 126MB L2.
__device__ __half g_nhwc[(size_t)BB * HWSZ * CC];

// NCHW [B,C,H,W] fp32 -> NHWC [B,H,W,C] fp16.
// Tile: 64 channels x 32 hw. Stores are half2 (2 adjacent channels) so each
// warp writes 128 contiguous bytes.
__global__ void nchw_to_nhwc(const float* __restrict__ in) {
    __shared__ float tile[64][33];
    const int b   = blockIdx.z;
    const int hw0 = blockIdx.x * 32;
    const int c0  = blockIdx.y * 64;
    const int tx = threadIdx.x, ty = threadIdx.y;
    const float* src = in + (size_t)b * CC * HWSZ;
    __half* dst = g_nhwc + (size_t)b * HWSZ * CC;
#pragma unroll
    for (int k = 0; k < 8; k++) {
        const int c = ty + k * 8;
        tile[c][tx] = src[(size_t)(c0 + c) * HWSZ + hw0 + tx];
    }
    __syncthreads();
#pragma unroll
    for (int k = 0; k < 4; k++) {
        const int hw = ty + k * 8;
        const __half2 v = __floats2half2_rn(tile[2 * tx][hw], tile[2 * tx + 1][hw]);
        *(__half2*)(dst + (size_t)(hw0 + hw) * CC + c0 + 2 * tx) = v;
    }
}

// One block per roi. blockDim = (32, 8): x = channel group (4 ch via 8B load),
// y = bin slot. Two channel halves of 128; results staged in smem in output
// layout, then copied out linearly (fully coalesced).
__global__ __launch_bounds__(256) void roi_align_kernel(
    const float* __restrict__ rois, float* __restrict__ out) {
    const int n = blockIdx.x;

    __shared__ int   s_i0[28];    // [0..13] y0, [14..27] x0
    __shared__ float s_l[28];     // frac part
    __shared__ int   s_v[28];     // valid flag
    __shared__ int   s_b;
    __shared__ float sbuf[128 * NBINS];   // 25,088 B

    const int tx = threadIdx.x, ty = threadIdx.y;
    const int tid = ty * 32 + tx;

    if (tid < 28) {
        const bool isx = tid >= 14;
        const int j = isx ? tid - 14 : tid;
        const float lo = rois[n * 5 + (isx ? 1 : 2)] * SPATIAL_SCALE;
        const float hi = rois[n * 5 + (isx ? 3 : 4)] * SPATIAL_SCALE;
        const float sz  = fmaxf(hi - lo, 1.0f);
        const float bin = sz * (1.0f / (float)OUT_HW);
        const float p = ((float)j + 0.5f) * 0.5f;
        const float coord = lo + p * bin;
        const int lim = isx ? WW : HH;
        const int valid = (coord > -1.0f) && (coord < (float)lim);
        float cc = fminf(fmaxf(coord, 0.0f), (float)(lim - 1));
        float c0 = fminf(floorf(cc), (float)(lim - 2));
        s_i0[tid] = (int)c0;
        s_l[tid]  = cc - c0;
        s_v[tid]  = valid;
    }
    if (tid == 0) s_b = (int)rois[n * 5 + 0];
    __syncthreads();

    const __half* fbase = g_nhwc + (size_t)s_b * HWSZ * CC;

    for (int cg = 0; cg < 2; cg++) {
        const int c = cg * 128 + tx * 4;

        for (int bin = ty; bin < NBINS; bin += 8) {
            const int ph = bin / 7;
            const int pw = bin - ph * 7;
            float a0 = 0.f, a1 = 0.f, a2 = 0.f, a3 = 0.f;
#pragma unroll
            for (int sy = 0; sy < 2; sy++) {
#pragma unroll
                for (int sx = 0; sx < 2; sx++) {
                    const int jy = ph * 2 + sy;
                    const int jx = 14 + pw * 2 + sx;
                    if (s_v[jy] && s_v[jx]) {
                        const int   y0 = s_i0[jy];
                        const int   x0 = s_i0[jx];
                        const float ly = s_l[jy];
                        const float lx = s_l[jx];
                        const float hy = 1.0f - ly, hx = 1.0f - lx;
                        const __half* p00 =
                            fbase + ((size_t)(y0 * WW + x0)) * CC + c;
                        const uint2 u00 = *(const uint2*)(p00);
                        const uint2 u01 = *(const uint2*)(p00 + CC);
                        const uint2 u10 = *(const uint2*)(p00 + (size_t)WW * CC);
                        const uint2 u11 = *(const uint2*)(p00 + (size_t)WW * CC + CC);
                        const float w00 = hy * hx, w01 = hy * lx;
                        const float w10 = ly * hx, w11 = ly * lx;
                        const float2 f00a = __half22float2(*(const __half2*)&u00.x);
                        const float2 f00b = __half22float2(*(const __half2*)&u00.y);
                        const float2 f01a = __half22float2(*(const __half2*)&u01.x);
                        const float2 f01b = __half22float2(*(const __half2*)&u01.y);
                        const float2 f10a = __half22float2(*(const __half2*)&u10.x);
                        const float2 f10b = __half22float2(*(const __half2*)&u10.y);
                        const float2 f11a = __half22float2(*(const __half2*)&u11.x);
                        const float2 f11b = __half22float2(*(const __half2*)&u11.y);
                        a0 += w00 * f00a.x + w01 * f01a.x + w10 * f10a.x + w11 * f11a.x;
                        a1 += w00 * f00a.y + w01 * f01a.y + w10 * f10a.y + w11 * f11a.y;
                        a2 += w00 * f00b.x + w01 * f01b.x + w10 * f10b.x + w11 * f11b.x;
                        a3 += w00 * f00b.y + w01 * f01b.y + w10 * f10b.y + w11 * f11b.y;
                    }
                }
            }
            const int cl = tx * 4;
            sbuf[(cl + 0) * NBINS + bin] = a0 * 0.25f;
            sbuf[(cl + 1) * NBINS + bin] = a1 * 0.25f;
            sbuf[(cl + 2) * NBINS + bin] = a2 * 0.25f;
            sbuf[(cl + 3) * NBINS + bin] = a3 * 0.25f;
        }
        __syncthreads();

        float* o = out + (size_t)n * (CC * NBINS) + (size_t)cg * 128 * NBINS;
        for (int i = tid; i < 128 * NBINS; i += 256) o[i] = sbuf[i];
        __syncthreads();
    }
}

extern "C" void kernel_launch(void* const* d_in, const int* in_sizes, int n_in,
                              void* d_out, int out_size) {
    const float* features = (const float*)d_in[0];
    const float* rois     = (const float*)d_in[1];
    float* out            = (float*)d_out;
    const int nrois = in_sizes[1] / 5;

    dim3 tgrid(HWSZ / 32, CC / 64, BB);   // 1700 x 4 x 4
    nchw_to_nhwc<<<tgrid, dim3(32, 8)>>>(features);
    roi_align_kernel<<<nrois, dim3(32, 8)>>>(rois, out);
}

// round 6
// speedup vs baseline: 1.6864x; 1.1943x over previous
#include <cuda_runtime.h>
#include <cuda_fp16.h>

#define OUT_HW 7
#define NBINS 49
#define SPATIAL_SCALE 0.25f
#define CC 256
#define HH 200
#define WW 272
#define BB 4
#define HWSZ (HH * WW)

// Scratch: NHWC fp16 copy of features (~111 MB).
__device__ __half g_nhwc[(size_t)BB * HWSZ * CC];

// NCHW [B,C,H,W] fp32 -> NHWC [B,H,W,C] fp16.
__global__ void nchw_to_nhwc(const float* __restrict__ in) {
    __shared__ float tile[64][33];
    const int b   = blockIdx.z;
    const int hw0 = blockIdx.x * 32;
    const int c0  = blockIdx.y * 64;
    const int tx = threadIdx.x, ty = threadIdx.y;
    const float* src = in + (size_t)b * CC * HWSZ;
    __half* dst = g_nhwc + (size_t)b * HWSZ * CC;
#pragma unroll
    for (int k = 0; k < 8; k++) {
        const int c = ty + k * 8;
        tile[c][tx] = src[(size_t)(c0 + c) * HWSZ + hw0 + tx];
    }
    __syncthreads();
#pragma unroll
    for (int k = 0; k < 4; k++) {
        const int hw = ty + k * 8;
        const __half2 v = __floats2half2_rn(tile[2 * tx][hw], tile[2 * tx + 1][hw]);
        *(__half2*)(dst + (size_t)(hw0 + hw) * CC + c0 + 2 * tx) = v;
    }
}

// One block per (roi, channel-half). blockDim=(32,8): x = 4-channel group,
// y = bin slot. Results staged in smem in output layout, float4 copy-out.
__global__ __launch_bounds__(256) void roi_align_kernel(
    const float* __restrict__ rois, float* __restrict__ out) {
    const int n  = blockIdx.x;
    const int cg = blockIdx.y;

    __shared__ __align__(16) float sbuf[128 * NBINS];  // 25,088 B, 16B-aligned
    __shared__ int   s_i0[28];    // [0..13] y0, [14..27] x0
    __shared__ float s_l[28];     // frac part
    __shared__ int   s_v[28];     // valid flag
    __shared__ int   s_b;

    const int tx = threadIdx.x, ty = threadIdx.y;
    const int tid = ty * 32 + tx;

    if (tid < 28) {
        const bool isx = tid >= 14;
        const int j = isx ? tid - 14 : tid;
        const float lo = rois[n * 5 + (isx ? 1 : 2)] * SPATIAL_SCALE;
        const float hi = rois[n * 5 + (isx ? 3 : 4)] * SPATIAL_SCALE;
        const float sz  = fmaxf(hi - lo, 1.0f);
        const float bin = sz * (1.0f / (float)OUT_HW);
        const float p = ((float)j + 0.5f) * 0.5f;
        const float coord = lo + p * bin;
        const int lim = isx ? WW : HH;
        const int valid = (coord > -1.0f) && (coord < (float)lim);
        float cc = fminf(fmaxf(coord, 0.0f), (float)(lim - 1));
        float c0 = fminf(floorf(cc), (float)(lim - 2));
        s_i0[tid] = (int)c0;
        s_l[tid]  = cc - c0;
        s_v[tid]  = valid;
    }
    if (tid == 0) s_b = (int)rois[n * 5 + 0];
    __syncthreads();

    const __half* fbase = g_nhwc + (size_t)s_b * HWSZ * CC + cg * 128 + tx * 4;

#pragma unroll 2
    for (int bin = ty; bin < NBINS; bin += 8) {
        const int ph = bin / 7;
        const int pw = bin - ph * 7;
        float a0 = 0.f, a1 = 0.f, a2 = 0.f, a3 = 0.f;
#pragma unroll
        for (int sy = 0; sy < 2; sy++) {
#pragma unroll
            for (int sx = 0; sx < 2; sx++) {
                const int jy = ph * 2 + sy;
                const int jx = 14 + pw * 2 + sx;
                if (s_v[jy] && s_v[jx]) {
                    const int   y0 = s_i0[jy];
                    const int   x0 = s_i0[jx];
                    const float ly = s_l[jy];
                    const float lx = s_l[jx];
                    const float hy = 1.0f - ly, hx = 1.0f - lx;
                    const __half* p00 = fbase + ((size_t)(y0 * WW + x0)) * CC;
                    const uint2 u00 = *(const uint2*)(p00);
                    const uint2 u01 = *(const uint2*)(p00 + CC);
                    const uint2 u10 = *(const uint2*)(p00 + (size_t)WW * CC);
                    const uint2 u11 = *(const uint2*)(p00 + (size_t)WW * CC + CC);
                    const float w00 = hy * hx, w01 = hy * lx;
                    const float w10 = ly * hx, w11 = ly * lx;
                    const float2 f00a = __half22float2(*(const __half2*)&u00.x);
                    const float2 f00b = __half22float2(*(const __half2*)&u00.y);
                    const float2 f01a = __half22float2(*(const __half2*)&u01.x);
                    const float2 f01b = __half22float2(*(const __half2*)&u01.y);
                    const float2 f10a = __half22float2(*(const __half2*)&u10.x);
                    const float2 f10b = __half22float2(*(const __half2*)&u10.y);
                    const float2 f11a = __half22float2(*(const __half2*)&u11.x);
                    const float2 f11b = __half22float2(*(const __half2*)&u11.y);
                    a0 += w00 * f00a.x + w01 * f01a.x + w10 * f10a.x + w11 * f11a.x;
                    a1 += w00 * f00a.y + w01 * f01a.y + w10 * f10a.y + w11 * f11a.y;
                    a2 += w00 * f00b.x + w01 * f01b.x + w10 * f10b.x + w11 * f11b.x;
                    a3 += w00 * f00b.y + w01 * f01b.y + w10 * f10b.y + w11 * f11b.y;
                }
            }
        }
        const int cl = tx * 4;
        sbuf[(cl + 0) * NBINS + bin] = a0 * 0.25f;
        sbuf[(cl + 1) * NBINS + bin] = a1 * 0.25f;
        sbuf[(cl + 2) * NBINS + bin] = a2 * 0.25f;
        sbuf[(cl + 3) * NBINS + bin] = a3 * 0.25f;
    }
    __syncthreads();

    // Coalesced float4 copy-out: this half is contiguous in the output.
    float4* o = (float4*)(out + (size_t)n * (CC * NBINS) + (size_t)cg * 128 * NBINS);
    const float4* s4 = (const float4*)sbuf;
#pragma unroll
    for (int i = tid; i < 128 * NBINS / 4; i += 256) o[i] = s4[i];
}

extern "C" void kernel_launch(void* const* d_in, const int* in_sizes, int n_in,
                              void* d_out, int out_size) {
    const float* features = (const float*)d_in[0];
    const float* rois     = (const float*)d_in[1];
    float* out            = (float*)d_out;
    const int nrois = in_sizes[1] / 5;

    dim3 tgrid(HWSZ / 32, CC / 64, BB);   // 1700 x 4 x 4
    nchw_to_nhwc<<<tgrid, dim3(32, 8)>>>(features);
    roi_align_kernel<<<dim3(nrois, 2), dim3(32, 8)>>>(rois, out);
}

// round 7
// speedup vs baseline: 1.7173x; 1.0184x over previous
#include <cuda_runtime.h>
#include <cuda_fp16.h>

#define OUT_HW 7
#define NBINS 49
#define SPATIAL_SCALE 0.25f
#define CC 256
#define HH 200
#define WW 272
#define BB 4
#define HWSZ (HH * WW)

// Scratch: NHWC fp16 copy of features (~111 MB).
__device__ __half g_nhwc[(size_t)BB * HWSZ * CC];

// NCHW [B,C,H,W] fp32 -> NHWC [B,H,W,C] fp16.
// Tile: 32 channels x 128 hw. Pad 129 => both smem phases conflict-free.
// Stores are uint4 (8 fp16 channels, 16B) in contiguous 64B runs per 4 lanes.
__global__ __launch_bounds__(256) void nchw_to_nhwc(const float* __restrict__ in) {
    __shared__ float tile[32][129];
    const int b   = blockIdx.z;
    const int hw0 = blockIdx.x * 128;
    const int c0  = blockIdx.y * 32;
    const int tx = threadIdx.x, ty = threadIdx.y;
    const int tid = ty * 32 + tx;
    const float* src = in + (size_t)b * CC * HWSZ + (size_t)c0 * HWSZ + hw0;
    __half* dst = g_nhwc + (size_t)b * HWSZ * CC + c0;

#pragma unroll
    for (int k = 0; k < 4; k++) {
        const int c = ty + k * 8;
        const float* s = src + (size_t)c * HWSZ;
#pragma unroll
        for (int m = 0; m < 4; m++) {
            tile[c][tx + m * 32] = s[tx + m * 32];
        }
    }
    __syncthreads();

#pragma unroll
    for (int i = 0; i < 2; i++) {
        const int s    = tid + i * 256;   // 0..511
        const int hw   = s >> 2;          // 0..127
        const int cgrp = s & 3;           // 8-channel group
        const int cb   = cgrp * 8;
        float v0 = tile[cb + 0][hw], v1 = tile[cb + 1][hw];
        float v2 = tile[cb + 2][hw], v3 = tile[cb + 3][hw];
        float v4 = tile[cb + 4][hw], v5 = tile[cb + 5][hw];
        float v6 = tile[cb + 6][hw], v7 = tile[cb + 7][hw];
        __half2 h0 = __floats2half2_rn(v0, v1);
        __half2 h1 = __floats2half2_rn(v2, v3);
        __half2 h2 = __floats2half2_rn(v4, v5);
        __half2 h3 = __floats2half2_rn(v6, v7);
        uint4 r;
        r.x = *(unsigned*)&h0; r.y = *(unsigned*)&h1;
        r.z = *(unsigned*)&h2; r.w = *(unsigned*)&h3;
        *(uint4*)(dst + (size_t)(hw0 + hw) * CC + cb) = r;
    }
}

// One block per (roi, channel-half). blockDim=(32,8): x = 4-channel group,
// y = bin slot. Results staged in smem in output layout, float4 copy-out.
__global__ __launch_bounds__(256) void roi_align_kernel(
    const float* __restrict__ rois, float* __restrict__ out) {
    const int n  = blockIdx.x;
    const int cg = blockIdx.y;

    __shared__ __align__(16) float sbuf[128 * NBINS];  // 25,088 B
    __shared__ int   s_i0[28];    // [0..13] y0, [14..27] x0
    __shared__ float s_l[28];     // frac part
    __shared__ int   s_v[28];     // valid flag
    __shared__ int   s_b;

    const int tx = threadIdx.x, ty = threadIdx.y;
    const int tid = ty * 32 + tx;

    if (tid < 28) {
        const bool isx = tid >= 14;
        const int j = isx ? tid - 14 : tid;
        const float lo = rois[n * 5 + (isx ? 1 : 2)] * SPATIAL_SCALE;
        const float hi = rois[n * 5 + (isx ? 3 : 4)] * SPATIAL_SCALE;
        const float sz  = fmaxf(hi - lo, 1.0f);
        const float bin = sz * (1.0f / (float)OUT_HW);
        const float p = ((float)j + 0.5f) * 0.5f;
        const float coord = lo + p * bin;
        const int lim = isx ? WW : HH;
        const int valid = (coord > -1.0f) && (coord < (float)lim);
        float cc = fminf(fmaxf(coord, 0.0f), (float)(lim - 1));
        float c0 = fminf(floorf(cc), (float)(lim - 2));
        s_i0[tid] = (int)c0;
        s_l[tid]  = cc - c0;
        s_v[tid]  = valid;
    }
    if (tid == 0) s_b = (int)rois[n * 5 + 0];
    __syncthreads();

    const __half* fbase = g_nhwc + (size_t)s_b * HWSZ * CC + cg * 128 + tx * 4;

#pragma unroll 2
    for (int bin = ty; bin < NBINS; bin += 8) {
        const int ph = bin / 7;
        const int pw = bin - ph * 7;
        float a0 = 0.f, a1 = 0.f, a2 = 0.f, a3 = 0.f;
#pragma unroll
        for (int sy = 0; sy < 2; sy++) {
#pragma unroll
            for (int sx = 0; sx < 2; sx++) {
                const int jy = ph * 2 + sy;
                const int jx = 14 + pw * 2 + sx;
                if (s_v[jy] && s_v[jx]) {
                    const int   y0 = s_i0[jy];
                    const int   x0 = s_i0[jx];
                    const float ly = s_l[jy];
                    const float lx = s_l[jx];
                    const float hy = 1.0f - ly, hx = 1.0f - lx;
                    const __half* p00 = fbase + ((size_t)(y0 * WW + x0)) * CC;
                    const uint2 u00 = *(const uint2*)(p00);
                    const uint2 u01 = *(const uint2*)(p00 + CC);
                    const uint2 u10 = *(const uint2*)(p00 + (size_t)WW * CC);
                    const uint2 u11 = *(const uint2*)(p00 + (size_t)WW * CC + CC);
                    const float w00 = hy * hx, w01 = hy * lx;
                    const float w10 = ly * hx, w11 = ly * lx;
                    const float2 f00a = __half22float2(*(const __half2*)&u00.x);
                    const float2 f00b = __half22float2(*(const __half2*)&u00.y);
                    const float2 f01a = __half22float2(*(const __half2*)&u01.x);
                    const float2 f01b = __half22float2(*(const __half2*)&u01.y);
                    const float2 f10a = __half22float2(*(const __half2*)&u10.x);
                    const float2 f10b = __half22float2(*(const __half2*)&u10.y);
                    const float2 f11a = __half22float2(*(const __half2*)&u11.x);
                    const float2 f11b = __half22float2(*(const __half2*)&u11.y);
                    a0 += w00 * f00a.x + w01 * f01a.x + w10 * f10a.x + w11 * f11a.x;
                    a1 += w00 * f00a.y + w01 * f01a.y + w10 * f10a.y + w11 * f11a.y;
                    a2 += w00 * f00b.x + w01 * f01b.x + w10 * f10b.x + w11 * f11b.x;
                    a3 += w00 * f00b.y + w01 * f01b.y + w10 * f10b.y + w11 * f11b.y;
                }
            }
        }
        const int cl = tx * 4;
        sbuf[(cl + 0) * NBINS + bin] = a0 * 0.25f;
        sbuf[(cl + 1) * NBINS + bin] = a1 * 0.25f;
        sbuf[(cl + 2) * NBINS + bin] = a2 * 0.25f;
        sbuf[(cl + 3) * NBINS + bin] = a3 * 0.25f;
    }
    __syncthreads();

    // Coalesced float4 copy-out: this half is contiguous in the output.
    float4* o = (float4*)(out + (size_t)n * (CC * NBINS) + (size_t)cg * 128 * NBINS);
    const float4* s4 = (const float4*)sbuf;
#pragma unroll
    for (int i = tid; i < 128 * NBINS / 4; i += 256) o[i] = s4[i];
}

extern "C" void kernel_launch(void* const* d_in, const int* in_sizes, int n_in,
                              void* d_out, int out_size) {
    const float* features = (const float*)d_in[0];
    const float* rois     = (const float*)d_in[1];
    float* out            = (float*)d_out;
    const int nrois = in_sizes[1] / 5;

    dim3 tgrid(HWSZ / 128, CC / 32, BB);   // 425 x 8 x 4
    nchw_to_nhwc<<<tgrid, dim3(32, 8)>>>(features);
    roi_align_kernel<<<dim3(nrois, 2), dim3(32, 8)>>>(rois, out);
}

// round 9
// speedup vs baseline: 1.7211x; 1.0022x over previous
#include <cuda_runtime.h>
#include <cuda_fp16.h>

#define OUT_HW 7
#define NBINS 49
#define NSAMP 196          // 49 bins * 4 samples
#define SPATIAL_SCALE 0.25f
#define CC 256
#define HH 200
#define WW 272
#define BB 4
#define HWSZ (HH * WW)

// Scratch: NHWC fp16 copy of features (~111 MB).
__device__ __half g_nhwc[(size_t)BB * HWSZ * CC];

// NCHW [B,C,H,W] fp32 -> NHWC [B,H,W,C] fp16. Already at DRAM roofline.
__global__ __launch_bounds__(256) void nchw_to_nhwc(const float* __restrict__ in) {
    __shared__ float tile[32][129];
    const int b   = blockIdx.z;
    const int hw0 = blockIdx.x * 128;
    const int c0  = blockIdx.y * 32;
    const int tx = threadIdx.x, ty = threadIdx.y;
    const int tid = ty * 32 + tx;
    const float* src = in + (size_t)b * CC * HWSZ + (size_t)c0 * HWSZ + hw0;
    __half* dst = g_nhwc + (size_t)b * HWSZ * CC + c0;

#pragma unroll
    for (int k = 0; k < 4; k++) {
        const int c = ty + k * 8;
        const float* s = src + (size_t)c * HWSZ;
#pragma unroll
        for (int m = 0; m < 4; m++) {
            tile[c][tx + m * 32] = s[tx + m * 32];
        }
    }
    __syncthreads();

#pragma unroll
    for (int i = 0; i < 2; i++) {
        const int s    = tid + i * 256;
        const int hw   = s >> 2;
        const int cgrp = s & 3;
        const int cb   = cgrp * 8;
        float v0 = tile[cb + 0][hw], v1 = tile[cb + 1][hw];
        float v2 = tile[cb + 2][hw], v3 = tile[cb + 3][hw];
        float v4 = tile[cb + 4][hw], v5 = tile[cb + 5][hw];
        float v6 = tile[cb + 6][hw], v7 = tile[cb + 7][hw];
        __half2 h0 = __floats2half2_rn(v0, v1);
        __half2 h1 = __floats2half2_rn(v2, v3);
        __half2 h2 = __floats2half2_rn(v4, v5);
        __half2 h3 = __floats2half2_rn(v6, v7);
        uint4 r;
        r.x = *(unsigned*)&h0; r.y = *(unsigned*)&h1;
        r.z = *(unsigned*)&h2; r.w = *(unsigned*)&h3;
        *(uint4*)(dst + (size_t)(hw0 + hw) * CC + cb) = r;
    }
}

__device__ __forceinline__ void acc4(const uint2 u, float w,
                                     float& a0, float& a1, float& a2, float& a3) {
    const float2 fa = __half22float2(*(const __half2*)&u.x);
    const float2 fb = __half22float2(*(const __half2*)&u.y);
    a0 = fmaf(w, fa.x, a0); a1 = fmaf(w, fa.y, a1);
    a2 = fmaf(w, fb.x, a2); a3 = fmaf(w, fb.y, a3);
}

// One block per (roi, channel-half). Branch-free mainloop driven by a
// precomputed per-sample {offset, weights} table (validity + 0.25 folded in).
__global__ __launch_bounds__(256) void roi_align_kernel(
    const float* __restrict__ rois, float* __restrict__ out) {
    const int n  = blockIdx.x;
    const int cg = blockIdx.y;

    __shared__ __align__(16) float sbuf[128 * NBINS];   // 25,088 B
    __shared__ __align__(16) float4 s_w[NSAMP];         // 3,136 B
    __shared__ int s_off[NSAMP];                        //   784 B
    __shared__ int s_b;

    const int tx = threadIdx.x, ty = threadIdx.y;
    const int tid = ty * 32 + tx;

    if (tid < NSAMP) {
        const int bin = tid >> 2;
        const int smp = tid & 3;
        const int ph = bin / 7, pw = bin - ph * 7;
        const int jy = ph * 2 + (smp >> 1);
        const int jx = pw * 2 + (smp & 1);

        const float x1r = rois[n * 5 + 1] * SPATIAL_SCALE;
        const float y1r = rois[n * 5 + 2] * SPATIAL_SCALE;
        const float x2r = rois[n * 5 + 3] * SPATIAL_SCALE;
        const float y2r = rois[n * 5 + 4] * SPATIAL_SCALE;
        const float bw = fmaxf(x2r - x1r, 1.0f) * (1.0f / 7.0f);
        const float bh = fmaxf(y2r - y1r, 1.0f) * (1.0f / 7.0f);

        const float yc = y1r + ((float)jy + 0.5f) * 0.5f * bh;
        const float xc = x1r + ((float)jx + 0.5f) * 0.5f * bw;
        const bool valid = (yc > -1.0f) && (yc < (float)HH) &&
                           (xc > -1.0f) && (xc < (float)WW);

        float y = fminf(fmaxf(yc, 0.0f), (float)(HH - 1));
        float x = fminf(fmaxf(xc, 0.0f), (float)(WW - 1));
        float y0f = fminf(floorf(y), (float)(HH - 2));
        float x0f = fminf(floorf(x), (float)(WW - 2));
        const float ly = y - y0f, lx = x - x0f;
        const float hy = 1.0f - ly, hx = 1.0f - lx;

        const float vm = valid ? 0.25f : 0.0f;   // fold mean + validity
        s_w[tid] = make_float4(hy * hx * vm, hy * lx * vm,
                               ly * hx * vm, ly * lx * vm);
        s_off[tid] = ((int)y0f * WW + (int)x0f) * CC;
    }
    if (tid == 0) s_b = (int)rois[n * 5 + 0];
    __syncthreads();

    const __half* fbase = g_nhwc + (size_t)s_b * HWSZ * CC + cg * 128 + tx * 4;

#pragma unroll 2
    for (int bin = ty; bin < NBINS; bin += 8) {
        float a0 = 0.f, a1 = 0.f, a2 = 0.f, a3 = 0.f;
#pragma unroll
        for (int sp = 0; sp < 2; sp++) {
            const int iA = bin * 4 + sp * 2;
            const int iB = iA + 1;
            const __half* pA = fbase + s_off[iA];
            const __half* pB = fbase + s_off[iB];
            const float4 wA = s_w[iA];
            const float4 wB = s_w[iB];
            // 8 independent unconditional gathers
            const uint2 uA0 = *(const uint2*)(pA);
            const uint2 uA1 = *(const uint2*)(pA + CC);
            const uint2 uA2 = *(const uint2*)(pA + (size_t)WW * CC);
            const uint2 uA3 = *(const uint2*)(pA + (size_t)WW * CC + CC);
            const uint2 uB0 = *(const uint2*)(pB);
            const uint2 uB1 = *(const uint2*)(pB + CC);
            const uint2 uB2 = *(const uint2*)(pB + (size_t)WW * CC);
            const uint2 uB3 = *(const uint2*)(pB + (size_t)WW * CC + CC);
            acc4(uA0, wA.x, a0, a1, a2, a3);
            acc4(uA1, wA.y, a0, a1, a2, a3);
            acc4(uA2, wA.z, a0, a1, a2, a3);
            acc4(uA3, wA.w, a0, a1, a2, a3);
            acc4(uB0, wB.x, a0, a1, a2, a3);
            acc4(uB1, wB.y, a0, a1, a2, a3);
            acc4(uB2, wB.z, a0, a1, a2, a3);
            acc4(uB3, wB.w, a0, a1, a2, a3);
        }
        const int cl = tx * 4;
        sbuf[(cl + 0) * NBINS + bin] = a0;
        sbuf[(cl + 1) * NBINS + bin] = a1;
        sbuf[(cl + 2) * NBINS + bin] = a2;
        sbuf[(cl + 3) * NBINS + bin] = a3;
    }
    __syncthreads();

    // Coalesced float4 copy-out: this half is contiguous in the output.
    float4* o = (float4*)(out + (size_t)n * (CC * NBINS) + (size_t)cg * 128 * NBINS);
    const float4* s4 = (const float4*)sbuf;
#pragma unroll
    for (int i = tid; i < 128 * NBINS / 4; i += 256) o[i] = s4[i];
}

extern "C" void kernel_launch(void* const* d_in, const int* in_sizes, int n_in,
                              void* d_out, int out_size) {
    const float* features = (const float*)d_in[0];
    const float* rois     = (const float*)d_in[1];
    float* out            = (float*)d_out;
    const int nrois = in_sizes[1] / 5;

    dim3 tgrid(HWSZ / 128, CC / 32, BB);   // 425 x 8 x 4
    nchw_to_nhwc<<<tgrid, dim3(32, 8)>>>(features);
    roi_align_kernel<<<dim3(nrois, 2), dim3(32, 8)>>>(rois, out);
}